// round 9
// baseline (speedup 1.0000x reference)
#include <cuda_runtime.h>
#include <float.h>
#include <stdint.h>

#define BB 32
#define NN 2048
#define TPB 64
#define PPT 8
#define CHUNK (TPB*PPT)        // 512 sources per CTA
#define NCHUNK (NN/CHUNK)      // 4
#define NHALF 4
#define HALFN (NN/NHALF)       // 512 targets per CTA
#define TILE 256
#define NPAIR (TILE/2)         // 128 pairs per tile
#define NOCTO (TILE/8)         // 32 octos per tile
#define NTILE (HALFN/TILE)     // 2
#define BIGF 1e10f

// Static scratch (no allocations allowed).
__device__ float         g_val[2*NHALF*BB*NN];   // stuffed best key per (dir,half,b,src)
__device__ unsigned int  g_idx[2*NHALF*BB*NN];   // winning-octo base index (absolute)
__device__ unsigned char g_hit[2][BB*NN];        // zeroed inside nl_scan each replay
__device__ float4        g_red4[2][BB][4];       // per-quarter {sum, cnt, hit?, 0}

// ---- f32x2 packed helpers (sm_103a) ----
__device__ __forceinline__ unsigned long long pk2(float lo, float hi) {
    unsigned long long r;
    asm("mov.b64 %0, {%1, %2};" : "=l"(r) : "f"(lo), "f"(hi));
    return r;
}
__device__ __forceinline__ void upk2(unsigned long long v, float& lo, float& hi) {
    asm("mov.b64 {%0, %1}, %2;" : "=f"(lo), "=f"(hi) : "l"(v));
}
__device__ __forceinline__ unsigned long long fma2(unsigned long long a,
                                                   unsigned long long b,
                                                   unsigned long long c) {
    unsigned long long d;
    asm("fma.rn.f32x2 %0, %1, %2, %3;" : "=l"(d) : "l"(a), "l"(b), "l"(c));
    return d;
}

// Scan: z = dir*NHALF + half. Each CTA: 512 sources vs 512 targets.
// Octo tournament: raw min over 8 targets (7 FMNMX), stuff 6-bit (tile|octo)
// into mantissa low bits (1 LOP3), accumulate across octos+tiles (1 FMNMX).
// c = ||t||^2 - 2 s.t (+BIG invalid target); per-source ||s||^2 const omitted
// (argmin invariant). Winning octo's 8 exact distances recomputed in nl_merge.
__global__ void __launch_bounds__(TPB) nl_scan(const float* __restrict__ X,
                                               const float* __restrict__ Y) {
    const int z    = blockIdx.z;           // dir*NHALF + half
    const int dir  = z >> 2;
    const int half = z & 3;
    const int b    = blockIdx.y;
    const float* S = dir ? Y : X;
    const float* T = dir ? X : Y;
    const float* sb = S + (size_t)b * NN * 3;
    const float* tb = T + ((size_t)b * NN + half * HALFN) * 3;

    __shared__ ulonglong2 shA[NPAIR];   // (-2x packed, -2y packed)
    __shared__ ulonglong2 shB[NPAIR];   // (-2z packed, tn packed (+BIG))

    const int tid  = threadIdx.x;
    const int base = blockIdx.x * CHUNK;

    // zero this CTA's 128-byte slice of the hit flags (1024 CTAs x 128 B total)
    {
        int bid = blockIdx.x + NCHUNK * (blockIdx.y + BB * blockIdx.z);
        if (tid < 8) ((uint4*)g_hit)[bid * 8 + tid] = make_uint4(0u,0u,0u,0u);
    }

    unsigned int mask;   // keep in a register: (bits & mask) | sv is one LOP3
    asm("mov.b32 %0, 0xFFFFFFC0;" : "=r"(mask));

    unsigned long long sx2[PPT], sy2[PPT], sz2[PPT];
#pragma unroll
    for (int p = 0; p < PPT; p++) {
        int i = base + tid + p * TPB;
        float a0 = sb[i*3+0], a1 = sb[i*3+1], a2 = sb[i*3+2];
        sx2[p] = pk2(a0, a0);
        sy2[p] = pk2(a1, a1);
        sz2[p] = pk2(a2, a2);
    }

    float best[PPT];
#pragma unroll
    for (int p = 0; p < PPT; p++) best[p] = FLT_MAX;

#pragma unroll
    for (int t = 0; t < NTILE; t++) {
        // tile load: 128 pairs, 64 threads -> 2 pairs per thread
#pragma unroll
        for (int k = 0; k < NPAIR/TPB; k++) {
            int j2 = tid + k * TPB;
            int j  = t * TILE + 2 * j2;
            float u0 = tb[j*3+0], u1 = tb[j*3+1], u2 = tb[j*3+2];
            float v0 = tb[j*3+3], v1 = tb[j*3+4], v2 = tb[j*3+5];
            float un = u0*u0 + u1*u1 + u2*u2;
            float vn = v0*v0 + v1*v1 + v2*v2;
            if ((u0 + u1 + u2) == 0.0f) un += BIGF;
            if ((v0 + v1 + v2) == 0.0f) vn += BIGF;
            shA[j2] = make_ulonglong2(pk2(-2.0f*u0, -2.0f*v0), pk2(-2.0f*u1, -2.0f*v1));
            shB[j2] = make_ulonglong2(pk2(-2.0f*u2, -2.0f*v2), pk2(un, vn));
        }
        __syncthreads();

#pragma unroll 2
        for (int o = 0; o < NOCTO; o++) {
            ulonglong2 a0 = shA[4*o],   b0 = shB[4*o];
            ulonglong2 a1 = shA[4*o+1], b1 = shB[4*o+1];
            ulonglong2 a2 = shA[4*o+2], b2 = shB[4*o+2];
            ulonglong2 a3 = shA[4*o+3], b3 = shB[4*o+3];
            unsigned int sv = (unsigned)((t << 5) | o);     // 6-bit tile|octo
#pragma unroll
            for (int p = 0; p < PPT; p++) {
                unsigned long long c0 =
                    fma2(sx2[p], a0.x, fma2(sy2[p], a0.y, fma2(sz2[p], b0.x, b0.y)));
                unsigned long long c1 =
                    fma2(sx2[p], a1.x, fma2(sy2[p], a1.y, fma2(sz2[p], b1.x, b1.y)));
                unsigned long long c2 =
                    fma2(sx2[p], a2.x, fma2(sy2[p], a2.y, fma2(sz2[p], b2.x, b2.y)));
                unsigned long long c3 =
                    fma2(sx2[p], a3.x, fma2(sy2[p], a3.y, fma2(sz2[p], b3.x, b3.y)));
                float l0,h0,l1,h1,l2,h2,l3,h3;
                upk2(c0, l0, h0); upk2(c1, l1, h1);
                upk2(c2, l2, h2); upk2(c3, l3, h3);
                float m = fminf(fminf(fminf(l0,h0), fminf(l1,h1)),
                                fminf(fminf(l2,h2), fminf(l3,h3)));   // 7 FMNMX
                unsigned int key = (__float_as_uint(m) & mask) | sv;  // 1 LOP3
                best[p] = fminf(best[p], __uint_as_float(key));       // 1 FMNMX
            }
        }
        __syncthreads();
    }

#pragma unroll
    for (int p = 0; p < PPT; p++) {
        unsigned int low6 = __float_as_uint(best[p]) & 0x3Fu;
        unsigned int idx  = half * HALFN + (low6 >> 5) * TILE + (low6 & 31u) * 8;
        int s = base + tid + p * TPB;
        size_t off = ((size_t)z * BB + b) * NN + s;
        g_val[off] = best[p];
        g_idx[off] = idx;
    }
}

// Merge: 256 blocks = (dir, b, quarter). Each block: 512 sources.
// Picks winning half, recomputes winning octo's 8 exact distances, applies
// validity, records hits, writes fixed-slot quarter partials (deterministic).
__global__ void __launch_bounds__(128) nl_merge(const float* __restrict__ X,
                                                const float* __restrict__ Y) {
    const int blk = blockIdx.x;       // 0..255
    const int qtr = blk & 3;
    const int b   = (blk >> 2) & 31;
    const int dir = blk >> 7;
    const float* S = dir ? Y : X;
    const float* T = dir ? X : Y;
    const float* sb = S + (size_t)b * NN * 3;
    const float* tv = T + (size_t)b * NN * 3;
    unsigned char* hit = &g_hit[dir][b * NN];
    const int tid = threadIdx.x;

    float sum = 0.0f; int cnt = 0;
#pragma unroll
    for (int it = 0; it < 4; it++) {
        int s = qtr * 512 + it * 128 + tid;
        float bkey = FLT_MAX; unsigned int obase = 0;
#pragma unroll
        for (int h = 0; h < NHALF; h++) {   // ascending: lowest half wins ties
            size_t o = ((size_t)(dir*NHALF + h) * BB + b) * NN + s;
            float k = g_val[o];
            if (k < bkey) { bkey = k; obase = g_idx[o]; }
        }
        float a0 = sb[s*3+0], a1 = sb[s*3+1], a2 = sb[s*3+2];
        if ((a0 + a1 + a2) != 0.0f) {                       // valid source
            float sn = a0*a0 + a1*a1 + a2*a2;
            float bd = FLT_MAX; unsigned int bi = obase;
#pragma unroll
            for (int i = 0; i < 8; i++) {                   // exact recompute of octo
                unsigned int idx = obase + i;
                float t0 = tv[idx*3+0], t1 = tv[idx*3+1], t2 = tv[idx*3+2];
                float tn = t0*t0 + t1*t1 + t2*t2;
                if ((t0 + t1 + t2) == 0.0f) tn += BIGF;
                float dot = fmaf(a0, t0, fmaf(a1, t1, a2 * t2));
                float d   = fmaf(-2.0f, dot, sn + tn);
                if (d < bd) { bd = d; bi = idx; }           // first-index tie-break
            }
            sum += bd;
            cnt += 1;
            hit[bi] = (unsigned char)1;                      // idempotent
        }
    }
#pragma unroll
    for (int o = 16; o > 0; o >>= 1) {
        sum += __shfl_down_sync(0xffffffffu, sum, o);
        cnt += __shfl_down_sync(0xffffffffu, cnt, o);
    }
    __shared__ float rs[4]; __shared__ int rc[4];
    if ((tid & 31) == 0) { rs[tid>>5] = sum; rc[tid>>5] = cnt; }
    __syncthreads();
    if (tid == 0) {
        float s2 = 0.0f; int c2 = 0;
#pragma unroll
        for (int w = 0; w < 4; w++) { s2 += rs[w]; c2 += rc[w]; }
        g_red4[dir][b][qtr] = make_float4(s2, (float)c2, 0.0f, 0.0f);
    }
}

// Final: one block, warp per batch. Popcount hits, combine quarter partials.
__global__ void __launch_bounds__(1024) nl_final(float* out, int out_size) {
    const int tid  = threadIdx.x;
    const int w    = tid >> 5;    // batch
    const int lane = tid & 31;

    const unsigned int* hy = (const unsigned int*)(g_hit[0] + w * NN);
    const unsigned int* hx = (const unsigned int*)(g_hit[1] + w * NN);
    int covc = 0, qualc = 0;
#pragma unroll
    for (int k = 0; k < NN/4/32; k++) {
        covc  += __popc(hy[lane + 32*k] & 0x01010101u);
        qualc += __popc(hx[lane + 32*k] & 0x01010101u);
    }
    float sxs = 0.0f, sys = 0.0f, cx = 0.0f, cy = 0.0f;
    if (lane < 4) {
        float4 r0 = g_red4[0][w][lane];
        float4 r1 = g_red4[1][w][lane];
        sxs = r0.x; cx = r0.y;
        sys = r1.x; cy = r1.y;
    }
#pragma unroll
    for (int o = 16; o > 0; o >>= 1) {
        covc  += __shfl_xor_sync(0xffffffffu, covc,  o);
        qualc += __shfl_xor_sync(0xffffffffu, qualc, o);
        sxs   += __shfl_xor_sync(0xffffffffu, sxs,   o);
        sys   += __shfl_xor_sync(0xffffffffu, sys,   o);
        cx    += __shfl_xor_sync(0xffffffffu, cx,    o);
        cy    += __shfl_xor_sync(0xffffffffu, cy,    o);
    }

    __shared__ float scd[BB], scov[BB], squal[BB];
    if (lane == 0) {
        scd[w]   = sxs / cx + sys / cy;
        scov[w]  = (float)covc  / cy;
        squal[w] = (float)qualc / cx;
    }
    __syncthreads();
    if (w == 0) {
        float cd = scd[lane], cov = scov[lane], qual = squal[lane];
#pragma unroll
        for (int o = 16; o > 0; o >>= 1) {
            cd   += __shfl_xor_sync(0xffffffffu, cd,   o);
            cov  += __shfl_xor_sync(0xffffffffu, cov,  o);
            qual += __shfl_xor_sync(0xffffffffu, qual, o);
        }
        if (lane == 0) {
            cd /= (float)BB; cov /= (float)BB; qual /= (float)BB;
            float val = cd - 1e-4f * cov - 1e-4f * qual;
            if (out_size > 0) out[0] = val;
            if (out_size > 1) out[1] = cd;
            if (out_size > 2) out[2] = cov;
            if (out_size > 3) out[3] = qual;
        }
    }
}

extern "C" void kernel_launch(void* const* d_in, const int* in_sizes, int n_in,
                              void* d_out, int out_size) {
    const float* x = (const float*)d_in[0];
    const float* y = (const float*)d_in[1];
    float* out = (float*)d_out;

    dim3 grid(NCHUNK, BB, 2 * NHALF);   // (4, 32, 8) = 1024 CTAs
    nl_scan<<<grid, TPB>>>(x, y);
    nl_merge<<<256, 128>>>(x, y);
    nl_final<<<1, 1024>>>(out, out_size);
}

// round 10
// speedup vs baseline: 1.0613x; 1.0613x over previous
#include <cuda_runtime.h>
#include <float.h>
#include <stdint.h>

#define BB 32
#define NN 2048
#define TPB 128
#define PPT 4
#define CHUNK (TPB*PPT)        // 512 sources per CTA
#define NCHUNK (NN/CHUNK)      // 4
#define NHALF 8
#define HALFN (NN/NHALF)       // 256 targets per CTA (one tile)
#define TILE 256
#define NPAIR (TILE/2)         // 128 pairs per tile (one per thread)
#define NOCTO (TILE/8)         // 32 octos per tile
#define BIGF 1e10f

// Static scratch (no allocations allowed).
__device__ float         g_val[2*NHALF*BB*NN];   // stuffed best key per (dir,half,b,src)
__device__ unsigned int  g_idx[2*NHALF*BB*NN];   // winning-octo base index (absolute)
__device__ unsigned char g_hit[2][BB*NN];        // zeroed inside nl_scan each replay
__device__ float4        g_red[2][BB];           // {sum_min, valid_cnt, hit_cnt, 0}

// ---- f32x2 packed helpers (sm_103a) ----
__device__ __forceinline__ unsigned long long pk2(float lo, float hi) {
    unsigned long long r;
    asm("mov.b64 %0, {%1, %2};" : "=l"(r) : "f"(lo), "f"(hi));
    return r;
}
__device__ __forceinline__ void upk2(unsigned long long v, float& lo, float& hi) {
    asm("mov.b64 {%0, %1}, %2;" : "=f"(lo), "=f"(hi) : "l"(v));
}
__device__ __forceinline__ unsigned long long fma2(unsigned long long a,
                                                   unsigned long long b,
                                                   unsigned long long c) {
    unsigned long long d;
    asm("fma.rn.f32x2 %0, %1, %2, %3;" : "=l"(d) : "l"(a), "l"(b), "l"(c));
    return d;
}

// Scan: z = dir*NHALF + half. Each CTA: 512 sources vs 256 targets (1 tile).
// Octo tournament: raw min over 8 targets (7 FMNMX), stuff 5-bit octo id into
// mantissa low bits (1 LOP3), accumulate (1 FMNMX).
// c = ||t||^2 - 2 s.t (+BIG invalid target); per-source ||s||^2 const omitted
// (argmin invariant). Winning octo's 8 exact distances recomputed in nl_merge.
__global__ void __launch_bounds__(TPB) nl_scan(const float* __restrict__ X,
                                               const float* __restrict__ Y) {
    const int z    = blockIdx.z;           // dir*NHALF + half
    const int dir  = z >> 3;
    const int half = z & 7;
    const int b    = blockIdx.y;
    const float* S = dir ? Y : X;
    const float* T = dir ? X : Y;
    const float* sb = S + (size_t)b * NN * 3;
    const float* tb = T + ((size_t)b * NN + half * HALFN) * 3;

    __shared__ ulonglong2 shA[NPAIR];   // (-2x packed, -2y packed)
    __shared__ ulonglong2 shB[NPAIR];   // (-2z packed, tn packed (+BIG))

    const int tid  = threadIdx.x;
    const int base = blockIdx.x * CHUNK;

    // zero this CTA's 64-byte slice of the hit flags (2048 CTAs x 64 B total)
    {
        int bid = blockIdx.x + NCHUNK * (blockIdx.y + BB * blockIdx.z);
        if (tid < 4) ((uint4*)g_hit)[bid * 4 + tid] = make_uint4(0u,0u,0u,0u);
    }

    unsigned int mask;   // keep in a register: (bits & mask) | o is one LOP3
    asm("mov.b32 %0, 0xFFFFFFE0;" : "=r"(mask));

    unsigned long long sx2[PPT], sy2[PPT], sz2[PPT];
#pragma unroll
    for (int p = 0; p < PPT; p++) {
        int i = base + tid + p * TPB;
        float a0 = sb[i*3+0], a1 = sb[i*3+1], a2 = sb[i*3+2];
        sx2[p] = pk2(a0, a0);
        sy2[p] = pk2(a1, a1);
        sz2[p] = pk2(a2, a2);
    }

    {   // tile load: one target-pair per thread (TILE == 2*TPB)
        int j = 2 * tid;
        float u0 = tb[j*3+0], u1 = tb[j*3+1], u2 = tb[j*3+2];
        float v0 = tb[j*3+3], v1 = tb[j*3+4], v2 = tb[j*3+5];
        float un = u0*u0 + u1*u1 + u2*u2;
        float vn = v0*v0 + v1*v1 + v2*v2;
        if ((u0 + u1 + u2) == 0.0f) un += BIGF;
        if ((v0 + v1 + v2) == 0.0f) vn += BIGF;
        shA[tid] = make_ulonglong2(pk2(-2.0f*u0, -2.0f*v0), pk2(-2.0f*u1, -2.0f*v1));
        shB[tid] = make_ulonglong2(pk2(-2.0f*u2, -2.0f*v2), pk2(un, vn));
    }
    __syncthreads();

    float best[PPT];
#pragma unroll
    for (int p = 0; p < PPT; p++) best[p] = FLT_MAX;

#pragma unroll 4
    for (int o = 0; o < NOCTO; o++) {
        ulonglong2 a0 = shA[4*o],   b0 = shB[4*o];
        ulonglong2 a1 = shA[4*o+1], b1 = shB[4*o+1];
        ulonglong2 a2 = shA[4*o+2], b2 = shB[4*o+2];
        ulonglong2 a3 = shA[4*o+3], b3 = shB[4*o+3];
#pragma unroll
        for (int p = 0; p < PPT; p++) {
            unsigned long long c0 =
                fma2(sx2[p], a0.x, fma2(sy2[p], a0.y, fma2(sz2[p], b0.x, b0.y)));
            unsigned long long c1 =
                fma2(sx2[p], a1.x, fma2(sy2[p], a1.y, fma2(sz2[p], b1.x, b1.y)));
            unsigned long long c2 =
                fma2(sx2[p], a2.x, fma2(sy2[p], a2.y, fma2(sz2[p], b2.x, b2.y)));
            unsigned long long c3 =
                fma2(sx2[p], a3.x, fma2(sy2[p], a3.y, fma2(sz2[p], b3.x, b3.y)));
            float l0,h0,l1,h1,l2,h2,l3,h3;
            upk2(c0, l0, h0); upk2(c1, l1, h1);
            upk2(c2, l2, h2); upk2(c3, l3, h3);
            float m = fminf(fminf(fminf(l0,h0), fminf(l1,h1)),
                            fminf(fminf(l2,h2), fminf(l3,h3)));     // 7 FMNMX
            unsigned int key = (__float_as_uint(m) & mask) | (unsigned)o;  // 1 LOP3
            best[p] = fminf(best[p], __uint_as_float(key));          // 1 FMNMX
        }
    }

#pragma unroll
    for (int p = 0; p < PPT; p++) {
        unsigned int octo = __float_as_uint(best[p]) & 0x1Fu;
        unsigned int idx  = half * HALFN + octo * 8;        // octo base, absolute
        int s = base + tid + p * TPB;
        size_t off = ((size_t)z * BB + b) * NN + s;
        g_val[off] = best[p];
        g_idx[off] = idx;
    }
}

// Merge: one block per (dir, b). Picks winning half per source (ascending,
// strict <), recomputes winning octo's 8 exact distances, applies validity,
// records hits, counts them, reduces sums. Deterministic fixed-slot output.
__global__ void __launch_bounds__(512) nl_merge(const float* __restrict__ X,
                                                const float* __restrict__ Y) {
    const int blk = blockIdx.x;       // 0..63
    const int dir = blk >> 5;
    const int b   = blk & 31;
    const float* S = dir ? Y : X;
    const float* T = dir ? X : Y;
    const float* sb = S + (size_t)b * NN * 3;
    const float* tv = T + (size_t)b * NN * 3;
    unsigned char* hit = &g_hit[dir][b * NN];
    const int tid = threadIdx.x;

    float sum = 0.0f; int cnt = 0;
#pragma unroll
    for (int it = 0; it < NN/512; it++) {
        int s = it * 512 + tid;
        float bkey = FLT_MAX; unsigned int obase = 0;
#pragma unroll
        for (int h = 0; h < NHALF; h++) {   // ascending: lowest half wins ties
            size_t o = ((size_t)(dir*NHALF + h) * BB + b) * NN + s;
            float k = g_val[o];
            if (k < bkey) { bkey = k; obase = g_idx[o]; }
        }
        float a0 = sb[s*3+0], a1 = sb[s*3+1], a2 = sb[s*3+2];
        if ((a0 + a1 + a2) != 0.0f) {                       // valid source
            float sn = a0*a0 + a1*a1 + a2*a2;
            float bd = FLT_MAX; unsigned int bi = obase;
#pragma unroll
            for (int i = 0; i < 8; i++) {                   // exact recompute of octo
                unsigned int idx = obase + i;
                float t0 = tv[idx*3+0], t1 = tv[idx*3+1], t2 = tv[idx*3+2];
                float tn = t0*t0 + t1*t1 + t2*t2;
                if ((t0 + t1 + t2) == 0.0f) tn += BIGF;
                float dot = fmaf(a0, t0, fmaf(a1, t1, a2 * t2));
                float d   = fmaf(-2.0f, dot, sn + tn);
                if (d < bd) { bd = d; bi = idx; }           // first-index tie-break
            }
            sum += bd;
            cnt += 1;
            hit[bi] = (unsigned char)1;                      // idempotent
        }
    }
    __syncthreads();                                         // hits all written

    int hc = 0;
    const unsigned int* hw = (const unsigned int*)hit;
    for (int k = tid; k < NN/4; k += 512) hc += __popc(hw[k] & 0x01010101u);

#pragma unroll
    for (int o = 16; o > 0; o >>= 1) {
        sum += __shfl_down_sync(0xffffffffu, sum, o);
        cnt += __shfl_down_sync(0xffffffffu, cnt, o);
        hc  += __shfl_down_sync(0xffffffffu, hc,  o);
    }
    __shared__ float rs[16]; __shared__ int rc[16], rh[16];
    if ((tid & 31) == 0) { rs[tid>>5] = sum; rc[tid>>5] = cnt; rh[tid>>5] = hc; }
    __syncthreads();
    if (tid == 0) {
        float s2 = 0.0f; int c2 = 0, h2 = 0;
#pragma unroll
        for (int w = 0; w < 16; w++) { s2 += rs[w]; c2 += rc[w]; h2 += rh[w]; }
        g_red[dir][b] = make_float4(s2, (float)c2, (float)h2, 0.0f);
    }
}

__global__ void nl_final(float* out, int out_size) {
    const int lane = threadIdx.x;    // 32 threads, one batch each
    float4 r0 = g_red[0][lane];      // dir0: x->y (sum xmin, nx, hit_y)
    float4 r1 = g_red[1][lane];      // dir1: y->x (sum ymin, ny, hit_x)
    float cd   = r0.x / r0.y + r1.x / r1.y;
    float cov  = r0.z / r1.y;        // hit_y / ny
    float qual = r1.z / r0.y;        // hit_x / nx
#pragma unroll
    for (int o = 16; o > 0; o >>= 1) {
        cd   += __shfl_xor_sync(0xffffffffu, cd,   o);
        cov  += __shfl_xor_sync(0xffffffffu, cov,  o);
        qual += __shfl_xor_sync(0xffffffffu, qual, o);
    }
    if (lane == 0) {
        cd /= (float)BB; cov /= (float)BB; qual /= (float)BB;
        float val = cd - 1e-4f * cov - 1e-4f * qual;
        if (out_size > 0) out[0] = val;
        if (out_size > 1) out[1] = cd;
        if (out_size > 2) out[2] = cov;
        if (out_size > 3) out[3] = qual;
    }
}

extern "C" void kernel_launch(void* const* d_in, const int* in_sizes, int n_in,
                              void* d_out, int out_size) {
    const float* x = (const float*)d_in[0];
    const float* y = (const float*)d_in[1];
    float* out = (float*)d_out;

    dim3 grid(NCHUNK, BB, 2 * NHALF);   // (4, 32, 16) = 2048 CTAs
    nl_scan<<<grid, TPB>>>(x, y);
    nl_merge<<<64, 512>>>(x, y);
    nl_final<<<1, 32>>>(out, out_size);
}

// round 11
// speedup vs baseline: 1.1871x; 1.1185x over previous
#include <cuda_runtime.h>
#include <float.h>
#include <stdint.h>

#define BB 32
#define NN 2048
#define TPB 128
#define PPT 4
#define CHUNK (TPB*PPT)        // 512 sources per CTA
#define NCHUNK (NN/CHUNK)      // 4
#define NHALF 8
#define HALFN (NN/NHALF)       // 256 targets per CTA (one tile)
#define TILE 256
#define NPAIR (TILE/2)         // 128 pairs per tile (one per thread)
#define NOCTO (TILE/8)         // 32 octos per tile
#define BIGF 1e10f

// Static scratch (no allocations allowed).
__device__ float         g_val[2*NHALF*BB*NN];   // stuffed best key per (dir,half,b,src)
__device__ unsigned char g_hit[2][BB*NN];        // zeroed inside nl_scan each replay
__device__ float4        g_red4[2][BB][4];       // per-quarter {sum, cnt, 0, 0}

// ---- f32x2 packed helpers (sm_103a) ----
__device__ __forceinline__ unsigned long long pk2(float lo, float hi) {
    unsigned long long r;
    asm("mov.b64 %0, {%1, %2};" : "=l"(r) : "f"(lo), "f"(hi));
    return r;
}
__device__ __forceinline__ void upk2(unsigned long long v, float& lo, float& hi) {
    asm("mov.b64 {%0, %1}, %2;" : "=f"(lo), "=f"(hi) : "l"(v));
}
__device__ __forceinline__ unsigned long long fma2(unsigned long long a,
                                                   unsigned long long b,
                                                   unsigned long long c) {
    unsigned long long d;
    asm("fma.rn.f32x2 %0, %1, %2, %3;" : "=l"(d) : "l"(a), "l"(b), "l"(c));
    return d;
}

// Scan: z = dir*NHALF + half. Each CTA: 512 sources vs 256 targets (1 tile).
// Octo tournament: raw min over 8 targets (7 FMNMX), stuff 5-bit octo id into
// mantissa low bits (1 LOP3), accumulate (1 FMNMX). Only the key is stored;
// merge reconstructs the octo base from (winning half, key low bits).
// c = ||t||^2 - 2 s.t (+BIG invalid target); per-source ||s||^2 const omitted
// (argmin invariant). Winning octo's 8 exact distances recomputed in nl_merge.
__global__ void __launch_bounds__(TPB) nl_scan(const float* __restrict__ X,
                                               const float* __restrict__ Y) {
    const int z    = blockIdx.z;           // dir*NHALF + half
    const int dir  = z >> 3;
    const int half = z & 7;
    const int b    = blockIdx.y;
    const float* S = dir ? Y : X;
    const float* T = dir ? X : Y;
    const float* sb = S + (size_t)b * NN * 3;
    const float* tb = T + ((size_t)b * NN + half * HALFN) * 3;

    __shared__ ulonglong2 shA[NPAIR];   // (-2x packed, -2y packed)
    __shared__ ulonglong2 shB[NPAIR];   // (-2z packed, tn packed (+BIG))

    const int tid  = threadIdx.x;
    const int base = blockIdx.x * CHUNK;

    // zero this CTA's 64-byte slice of the hit flags (2048 CTAs x 64 B total)
    {
        int bid = blockIdx.x + NCHUNK * (blockIdx.y + BB * blockIdx.z);
        if (tid < 4) ((uint4*)g_hit)[bid * 4 + tid] = make_uint4(0u,0u,0u,0u);
    }

    unsigned int mask;   // keep in a register: (bits & mask) | o is one LOP3
    asm("mov.b32 %0, 0xFFFFFFE0;" : "=r"(mask));

    unsigned long long sx2[PPT], sy2[PPT], sz2[PPT];
#pragma unroll
    for (int p = 0; p < PPT; p++) {
        int i = base + tid + p * TPB;
        float a0 = sb[i*3+0], a1 = sb[i*3+1], a2 = sb[i*3+2];
        sx2[p] = pk2(a0, a0);
        sy2[p] = pk2(a1, a1);
        sz2[p] = pk2(a2, a2);
    }

    {   // tile load: one target-pair per thread (TILE == 2*TPB)
        int j = 2 * tid;
        float u0 = tb[j*3+0], u1 = tb[j*3+1], u2 = tb[j*3+2];
        float v0 = tb[j*3+3], v1 = tb[j*3+4], v2 = tb[j*3+5];
        float un = u0*u0 + u1*u1 + u2*u2;
        float vn = v0*v0 + v1*v1 + v2*v2;
        if ((u0 + u1 + u2) == 0.0f) un += BIGF;
        if ((v0 + v1 + v2) == 0.0f) vn += BIGF;
        shA[tid] = make_ulonglong2(pk2(-2.0f*u0, -2.0f*v0), pk2(-2.0f*u1, -2.0f*v1));
        shB[tid] = make_ulonglong2(pk2(-2.0f*u2, -2.0f*v2), pk2(un, vn));
    }
    __syncthreads();

    float best[PPT];
#pragma unroll
    for (int p = 0; p < PPT; p++) best[p] = FLT_MAX;

#pragma unroll 4
    for (int o = 0; o < NOCTO; o++) {
        ulonglong2 a0 = shA[4*o],   b0 = shB[4*o];
        ulonglong2 a1 = shA[4*o+1], b1 = shB[4*o+1];
        ulonglong2 a2 = shA[4*o+2], b2 = shB[4*o+2];
        ulonglong2 a3 = shA[4*o+3], b3 = shB[4*o+3];
#pragma unroll
        for (int p = 0; p < PPT; p++) {
            unsigned long long c0 =
                fma2(sx2[p], a0.x, fma2(sy2[p], a0.y, fma2(sz2[p], b0.x, b0.y)));
            unsigned long long c1 =
                fma2(sx2[p], a1.x, fma2(sy2[p], a1.y, fma2(sz2[p], b1.x, b1.y)));
            unsigned long long c2 =
                fma2(sx2[p], a2.x, fma2(sy2[p], a2.y, fma2(sz2[p], b2.x, b2.y)));
            unsigned long long c3 =
                fma2(sx2[p], a3.x, fma2(sy2[p], a3.y, fma2(sz2[p], b3.x, b3.y)));
            float l0,h0,l1,h1,l2,h2,l3,h3;
            upk2(c0, l0, h0); upk2(c1, l1, h1);
            upk2(c2, l2, h2); upk2(c3, l3, h3);
            float m = fminf(fminf(fminf(l0,h0), fminf(l1,h1)),
                            fminf(fminf(l2,h2), fminf(l3,h3)));     // 7 FMNMX
            unsigned int key = (__float_as_uint(m) & mask) | (unsigned)o;  // 1 LOP3
            best[p] = fminf(best[p], __uint_as_float(key));          // 1 FMNMX
        }
    }

#pragma unroll
    for (int p = 0; p < PPT; p++) {
        int s = base + tid + p * TPB;
        g_val[((size_t)z * BB + b) * NN + s] = best[p];
    }
}

// Merge: 256 blocks = (dir, b, quarter) x 128 threads, 512 sources each.
// Picks winning half (ascending, strict < -> lowest half wins ties),
// reconstructs octo base from (half, key low 5 bits), recomputes 8 exact
// distances, applies validity, records hits, writes fixed-slot partials.
__global__ void __launch_bounds__(128) nl_merge(const float* __restrict__ X,
                                                const float* __restrict__ Y) {
    const int blk = blockIdx.x;       // 0..255
    const int qtr = blk & 3;
    const int b   = (blk >> 2) & 31;
    const int dir = blk >> 7;
    const float* S = dir ? Y : X;
    const float* T = dir ? X : Y;
    const float* sb = S + (size_t)b * NN * 3;
    const float* tv = T + (size_t)b * NN * 3;
    unsigned char* hit = &g_hit[dir][b * NN];
    const int tid = threadIdx.x;

    float sum = 0.0f; int cnt = 0;
#pragma unroll
    for (int it = 0; it < 4; it++) {
        int s = qtr * 512 + it * 128 + tid;
        float bkey = FLT_MAX; int bh = 0;
#pragma unroll
        for (int h = 0; h < NHALF; h++) {   // ascending: lowest half wins ties
            float k = g_val[((size_t)(dir*NHALF + h) * BB + b) * NN + s];
            if (k < bkey) { bkey = k; bh = h; }
        }
        unsigned int obase = (unsigned)bh * HALFN + (__float_as_uint(bkey) & 0x1Fu) * 8;
        float a0 = sb[s*3+0], a1 = sb[s*3+1], a2 = sb[s*3+2];
        if ((a0 + a1 + a2) != 0.0f) {                       // valid source
            float sn = a0*a0 + a1*a1 + a2*a2;
            float bd = FLT_MAX; unsigned int bi = obase;
#pragma unroll
            for (int i = 0; i < 8; i++) {                   // exact recompute of octo
                unsigned int idx = obase + i;
                float t0 = tv[idx*3+0], t1 = tv[idx*3+1], t2 = tv[idx*3+2];
                float tn = t0*t0 + t1*t1 + t2*t2;
                if ((t0 + t1 + t2) == 0.0f) tn += BIGF;
                float dot = fmaf(a0, t0, fmaf(a1, t1, a2 * t2));
                float d   = fmaf(-2.0f, dot, sn + tn);
                if (d < bd) { bd = d; bi = idx; }           // first-index tie-break
            }
            sum += bd;
            cnt += 1;
            hit[bi] = (unsigned char)1;                      // idempotent
        }
    }
#pragma unroll
    for (int o = 16; o > 0; o >>= 1) {
        sum += __shfl_down_sync(0xffffffffu, sum, o);
        cnt += __shfl_down_sync(0xffffffffu, cnt, o);
    }
    __shared__ float rs[4]; __shared__ int rc[4];
    if ((tid & 31) == 0) { rs[tid>>5] = sum; rc[tid>>5] = cnt; }
    __syncthreads();
    if (tid == 0) {
        float s2 = 0.0f; int c2 = 0;
#pragma unroll
        for (int w = 0; w < 4; w++) { s2 += rs[w]; c2 += rc[w]; }
        g_red4[dir][b][qtr] = make_float4(s2, (float)c2, 0.0f, 0.0f);
    }
}

// Final: one block, warp per batch. Popcount hits, combine quarter partials.
__global__ void __launch_bounds__(1024) nl_final(float* out, int out_size) {
    const int tid  = threadIdx.x;
    const int w    = tid >> 5;    // batch
    const int lane = tid & 31;

    const unsigned int* hy = (const unsigned int*)(g_hit[0] + w * NN);
    const unsigned int* hx = (const unsigned int*)(g_hit[1] + w * NN);
    int covc = 0, qualc = 0;
#pragma unroll
    for (int k = 0; k < NN/4/32; k++) {
        covc  += __popc(hy[lane + 32*k] & 0x01010101u);
        qualc += __popc(hx[lane + 32*k] & 0x01010101u);
    }
    float sxs = 0.0f, sys = 0.0f, cx = 0.0f, cy = 0.0f;
    if (lane < 4) {
        float4 r0 = g_red4[0][w][lane];
        float4 r1 = g_red4[1][w][lane];
        sxs = r0.x; cx = r0.y;
        sys = r1.x; cy = r1.y;
    }
#pragma unroll
    for (int o = 16; o > 0; o >>= 1) {
        covc  += __shfl_xor_sync(0xffffffffu, covc,  o);
        qualc += __shfl_xor_sync(0xffffffffu, qualc, o);
        sxs   += __shfl_xor_sync(0xffffffffu, sxs,   o);
        sys   += __shfl_xor_sync(0xffffffffu, sys,   o);
        cx    += __shfl_xor_sync(0xffffffffu, cx,    o);
        cy    += __shfl_xor_sync(0xffffffffu, cy,    o);
    }

    __shared__ float scd[BB], scov[BB], squal[BB];
    if (lane == 0) {
        scd[w]   = sxs / cx + sys / cy;
        scov[w]  = (float)covc  / cy;
        squal[w] = (float)qualc / cx;
    }
    __syncthreads();
    if (w == 0) {
        float cd = scd[lane], cov = scov[lane], qual = squal[lane];
#pragma unroll
        for (int o = 16; o > 0; o >>= 1) {
            cd   += __shfl_xor_sync(0xffffffffu, cd,   o);
            cov  += __shfl_xor_sync(0xffffffffu, cov,  o);
            qual += __shfl_xor_sync(0xffffffffu, qual, o);
        }
        if (lane == 0) {
            cd /= (float)BB; cov /= (float)BB; qual /= (float)BB;
            float val = cd - 1e-4f * cov - 1e-4f * qual;
            if (out_size > 0) out[0] = val;
            if (out_size > 1) out[1] = cd;
            if (out_size > 2) out[2] = cov;
            if (out_size > 3) out[3] = qual;
        }
    }
}

extern "C" void kernel_launch(void* const* d_in, const int* in_sizes, int n_in,
                              void* d_out, int out_size) {
    const float* x = (const float*)d_in[0];
    const float* y = (const float*)d_in[1];
    float* out = (float*)d_out;

    dim3 grid(NCHUNK, BB, 2 * NHALF);   // (4, 32, 16) = 2048 CTAs
    nl_scan<<<grid, TPB>>>(x, y);
    nl_merge<<<256, 128>>>(x, y);
    nl_final<<<1, 1024>>>(out, out_size);
}

// round 12
// speedup vs baseline: 1.2164x; 1.0247x over previous
#include <cuda_runtime.h>
#include <float.h>
#include <stdint.h>

#define BB 32
#define NN 2048
#define TPB 128
#define PPT 4
#define CHUNK (TPB*PPT)        // 512 sources per CTA
#define NCHUNK (NN/CHUNK)      // 4
#define NHALF 8
#define HALFN (NN/NHALF)       // 256 targets per CTA (one tile)
#define TILE 256
#define NPAIR (TILE/2)         // 128 pairs per tile (one per thread)
#define NOCTO (TILE/8)         // 32 octos per tile
#define BIGF 1e10f

// Static scratch (no allocations allowed).
// Interleaved key layout: one source's NHALF keys are contiguous (32 B) so the
// merge reads them with two LDG.128 instead of 8 scattered LDGs.
__device__ float         g_val[2][BB][NN][NHALF];
__device__ unsigned char g_hit[2][BB*NN];        // zeroed inside nl_scan each replay
__device__ float4        g_red4[2][BB][4];       // per-quarter {sum, cnt, 0, 0}

// ---- f32x2 packed helpers (sm_103a) ----
__device__ __forceinline__ unsigned long long pk2(float lo, float hi) {
    unsigned long long r;
    asm("mov.b64 %0, {%1, %2};" : "=l"(r) : "f"(lo), "f"(hi));
    return r;
}
__device__ __forceinline__ void upk2(unsigned long long v, float& lo, float& hi) {
    asm("mov.b64 {%0, %1}, %2;" : "=f"(lo), "=f"(hi) : "l"(v));
}
__device__ __forceinline__ unsigned long long fma2(unsigned long long a,
                                                   unsigned long long b,
                                                   unsigned long long c) {
    unsigned long long d;
    asm("fma.rn.f32x2 %0, %1, %2, %3;" : "=l"(d) : "l"(a), "l"(b), "l"(c));
    return d;
}

// Scan: z = dir*NHALF + half. Each CTA: 512 sources vs 256 targets (1 tile).
// Octo tournament: raw min over 8 targets (7 FMNMX), stuff 5-bit octo id into
// mantissa low bits (1 LOP3), accumulate (1 FMNMX). Only the key is stored;
// merge reconstructs the octo base from (winning half slot, key low bits).
// c = ||t||^2 - 2 s.t (+BIG invalid target); per-source ||s||^2 const omitted
// (argmin invariant). Winning octo's 8 exact distances recomputed in nl_merge.
__global__ void __launch_bounds__(TPB) nl_scan(const float* __restrict__ X,
                                               const float* __restrict__ Y) {
    const int z    = blockIdx.z;           // dir*NHALF + half
    const int dir  = z >> 3;
    const int half = z & 7;
    const int b    = blockIdx.y;
    const float* S = dir ? Y : X;
    const float* T = dir ? X : Y;
    const float* sb = S + (size_t)b * NN * 3;
    const float* tb = T + ((size_t)b * NN + half * HALFN) * 3;

    __shared__ ulonglong2 shA[NPAIR];   // (-2x packed, -2y packed)
    __shared__ ulonglong2 shB[NPAIR];   // (-2z packed, tn packed (+BIG))

    const int tid  = threadIdx.x;
    const int base = blockIdx.x * CHUNK;

    // zero this CTA's 64-byte slice of the hit flags (2048 CTAs x 64 B total)
    {
        int bid = blockIdx.x + NCHUNK * (blockIdx.y + BB * blockIdx.z);
        if (tid < 4) ((uint4*)g_hit)[bid * 4 + tid] = make_uint4(0u,0u,0u,0u);
    }

    unsigned int mask;   // keep in a register: (bits & mask) | o is one LOP3
    asm("mov.b32 %0, 0xFFFFFFE0;" : "=r"(mask));

    unsigned long long sx2[PPT], sy2[PPT], sz2[PPT];
#pragma unroll
    for (int p = 0; p < PPT; p++) {
        int i = base + tid + p * TPB;
        float a0 = sb[i*3+0], a1 = sb[i*3+1], a2 = sb[i*3+2];
        sx2[p] = pk2(a0, a0);
        sy2[p] = pk2(a1, a1);
        sz2[p] = pk2(a2, a2);
    }

    {   // tile load: one target-pair per thread (TILE == 2*TPB)
        int j = 2 * tid;
        float u0 = tb[j*3+0], u1 = tb[j*3+1], u2 = tb[j*3+2];
        float v0 = tb[j*3+3], v1 = tb[j*3+4], v2 = tb[j*3+5];
        float un = u0*u0 + u1*u1 + u2*u2;
        float vn = v0*v0 + v1*v1 + v2*v2;
        if ((u0 + u1 + u2) == 0.0f) un += BIGF;
        if ((v0 + v1 + v2) == 0.0f) vn += BIGF;
        shA[tid] = make_ulonglong2(pk2(-2.0f*u0, -2.0f*v0), pk2(-2.0f*u1, -2.0f*v1));
        shB[tid] = make_ulonglong2(pk2(-2.0f*u2, -2.0f*v2), pk2(un, vn));
    }
    __syncthreads();

    float best[PPT];
#pragma unroll
    for (int p = 0; p < PPT; p++) best[p] = FLT_MAX;

#pragma unroll 4
    for (int o = 0; o < NOCTO; o++) {
        ulonglong2 a0 = shA[4*o],   b0 = shB[4*o];
        ulonglong2 a1 = shA[4*o+1], b1 = shB[4*o+1];
        ulonglong2 a2 = shA[4*o+2], b2 = shB[4*o+2];
        ulonglong2 a3 = shA[4*o+3], b3 = shB[4*o+3];
#pragma unroll
        for (int p = 0; p < PPT; p++) {
            unsigned long long c0 =
                fma2(sx2[p], a0.x, fma2(sy2[p], a0.y, fma2(sz2[p], b0.x, b0.y)));
            unsigned long long c1 =
                fma2(sx2[p], a1.x, fma2(sy2[p], a1.y, fma2(sz2[p], b1.x, b1.y)));
            unsigned long long c2 =
                fma2(sx2[p], a2.x, fma2(sy2[p], a2.y, fma2(sz2[p], b2.x, b2.y)));
            unsigned long long c3 =
                fma2(sx2[p], a3.x, fma2(sy2[p], a3.y, fma2(sz2[p], b3.x, b3.y)));
            float l0,h0,l1,h1,l2,h2,l3,h3;
            upk2(c0, l0, h0); upk2(c1, l1, h1);
            upk2(c2, l2, h2); upk2(c3, l3, h3);
            float m = fminf(fminf(fminf(l0,h0), fminf(l1,h1)),
                            fminf(fminf(l2,h2), fminf(l3,h3)));     // 7 FMNMX
            unsigned int key = (__float_as_uint(m) & mask) | (unsigned)o;  // 1 LOP3
            best[p] = fminf(best[p], __uint_as_float(key));          // 1 FMNMX
        }
    }

#pragma unroll
    for (int p = 0; p < PPT; p++) {
        int s = base + tid + p * TPB;
        g_val[dir][b][s][half] = best[p];   // interleaved: 32B-strided per lane
    }
}

// Merge: 256 blocks = (dir, b, quarter) x 128 threads, 512 sources each.
// Loads a source's 8 half-keys as two float4 (coalesced). Picks winning half
// (ascending, strict < -> lowest half wins ties), reconstructs octo base from
// (half, key low 5 bits), recomputes 8 exact distances, applies validity,
// records hits, writes fixed-slot quarter partials (deterministic).
__global__ void __launch_bounds__(128) nl_merge(const float* __restrict__ X,
                                                const float* __restrict__ Y) {
    const int blk = blockIdx.x;       // 0..255
    const int qtr = blk & 3;
    const int b   = (blk >> 2) & 31;
    const int dir = blk >> 7;
    const float* S = dir ? Y : X;
    const float* T = dir ? X : Y;
    const float* sb = S + (size_t)b * NN * 3;
    const float* tv = T + (size_t)b * NN * 3;
    unsigned char* hit = &g_hit[dir][b * NN];
    const int tid = threadIdx.x;

    float sum = 0.0f; int cnt = 0;
#pragma unroll
    for (int it = 0; it < 4; it++) {
        int s = qtr * 512 + it * 128 + tid;
        const float4* kp = (const float4*)&g_val[dir][b][s][0];
        float4 k0 = kp[0];   // halves 0..3
        float4 k1 = kp[1];   // halves 4..7
        float bkey = k0.x; int bh = 0;
        if (k0.y < bkey) { bkey = k0.y; bh = 1; }
        if (k0.z < bkey) { bkey = k0.z; bh = 2; }
        if (k0.w < bkey) { bkey = k0.w; bh = 3; }
        if (k1.x < bkey) { bkey = k1.x; bh = 4; }
        if (k1.y < bkey) { bkey = k1.y; bh = 5; }
        if (k1.z < bkey) { bkey = k1.z; bh = 6; }
        if (k1.w < bkey) { bkey = k1.w; bh = 7; }
        unsigned int obase = (unsigned)bh * HALFN + (__float_as_uint(bkey) & 0x1Fu) * 8;
        float a0 = sb[s*3+0], a1 = sb[s*3+1], a2 = sb[s*3+2];
        if ((a0 + a1 + a2) != 0.0f) {                       // valid source
            float sn = a0*a0 + a1*a1 + a2*a2;
            float bd = FLT_MAX; unsigned int bi = obase;
#pragma unroll
            for (int i = 0; i < 8; i++) {                   // exact recompute of octo
                unsigned int idx = obase + i;
                float t0 = tv[idx*3+0], t1 = tv[idx*3+1], t2 = tv[idx*3+2];
                float tn = t0*t0 + t1*t1 + t2*t2;
                if ((t0 + t1 + t2) == 0.0f) tn += BIGF;
                float dot = fmaf(a0, t0, fmaf(a1, t1, a2 * t2));
                float d   = fmaf(-2.0f, dot, sn + tn);
                if (d < bd) { bd = d; bi = idx; }           // first-index tie-break
            }
            sum += bd;
            cnt += 1;
            hit[bi] = (unsigned char)1;                      // idempotent
        }
    }
#pragma unroll
    for (int o = 16; o > 0; o >>= 1) {
        sum += __shfl_down_sync(0xffffffffu, sum, o);
        cnt += __shfl_down_sync(0xffffffffu, cnt, o);
    }
    __shared__ float rs[4]; __shared__ int rc[4];
    if ((tid & 31) == 0) { rs[tid>>5] = sum; rc[tid>>5] = cnt; }
    __syncthreads();
    if (tid == 0) {
        float s2 = 0.0f; int c2 = 0;
#pragma unroll
        for (int w = 0; w < 4; w++) { s2 += rs[w]; c2 += rc[w]; }
        g_red4[dir][b][qtr] = make_float4(s2, (float)c2, 0.0f, 0.0f);
    }
}

// Final: one block, warp per batch. Popcount hits, combine quarter partials.
__global__ void __launch_bounds__(1024) nl_final(float* out, int out_size) {
    const int tid  = threadIdx.x;
    const int w    = tid >> 5;    // batch
    const int lane = tid & 31;

    const unsigned int* hy = (const unsigned int*)(g_hit[0] + w * NN);
    const unsigned int* hx = (const unsigned int*)(g_hit[1] + w * NN);
    int covc = 0, qualc = 0;
#pragma unroll
    for (int k = 0; k < NN/4/32; k++) {
        covc  += __popc(hy[lane + 32*k] & 0x01010101u);
        qualc += __popc(hx[lane + 32*k] & 0x01010101u);
    }
    float sxs = 0.0f, sys = 0.0f, cx = 0.0f, cy = 0.0f;
    if (lane < 4) {
        float4 r0 = g_red4[0][w][lane];
        float4 r1 = g_red4[1][w][lane];
        sxs = r0.x; cx = r0.y;
        sys = r1.x; cy = r1.y;
    }
#pragma unroll
    for (int o = 16; o > 0; o >>= 1) {
        covc  += __shfl_xor_sync(0xffffffffu, covc,  o);
        qualc += __shfl_xor_sync(0xffffffffu, qualc, o);
        sxs   += __shfl_xor_sync(0xffffffffu, sxs,   o);
        sys   += __shfl_xor_sync(0xffffffffu, sys,   o);
        cx    += __shfl_xor_sync(0xffffffffu, cx,    o);
        cy    += __shfl_xor_sync(0xffffffffu, cy,    o);
    }

    __shared__ float scd[BB], scov[BB], squal[BB];
    if (lane == 0) {
        scd[w]   = sxs / cx + sys / cy;
        scov[w]  = (float)covc  / cy;
        squal[w] = (float)qualc / cx;
    }
    __syncthreads();
    if (w == 0) {
        float cd = scd[lane], cov = scov[lane], qual = squal[lane];
#pragma unroll
        for (int o = 16; o > 0; o >>= 1) {
            cd   += __shfl_xor_sync(0xffffffffu, cd,   o);
            cov  += __shfl_xor_sync(0xffffffffu, cov,  o);
            qual += __shfl_xor_sync(0xffffffffu, qual, o);
        }
        if (lane == 0) {
            cd /= (float)BB; cov /= (float)BB; qual /= (float)BB;
            float val = cd - 1e-4f * cov - 1e-4f * qual;
            if (out_size > 0) out[0] = val;
            if (out_size > 1) out[1] = cd;
            if (out_size > 2) out[2] = cov;
            if (out_size > 3) out[3] = qual;
        }
    }
}

extern "C" void kernel_launch(void* const* d_in, const int* in_sizes, int n_in,
                              void* d_out, int out_size) {
    const float* x = (const float*)d_in[0];
    const float* y = (const float*)d_in[1];
    float* out = (float*)d_out;

    dim3 grid(NCHUNK, BB, 2 * NHALF);   // (4, 32, 16) = 2048 CTAs
    nl_scan<<<grid, TPB>>>(x, y);
    nl_merge<<<256, 128>>>(x, y);
    nl_final<<<1, 1024>>>(out, out_size);
}